// round 1
// baseline (speedup 1.0000x reference)
#include <cuda_runtime.h>
#include <cstdint>
#include <math.h>

#define TSTEPS 4096
#define DIN    512
#define FDIM   256
#define HID    200
#define G4     800
#define KDIM   40
#define NSLOT  128
#define EPSF   1e-12f
#define CLSZ   8
#define JPC    25     // hidden units per CTA
#define RPC    100    // gate rows per CTA

// ---------------- scratch (device globals; no allocation allowed) ----------------
__device__ float g_xs[TSTEPS * FDIM];
__device__ float g_gx[TSTEPS * G4];
__device__ float g_hid[TSTEPS * HID];
__device__ float g_keys[TSTEPS * KDIM];
__device__ float g_kn[TSTEPS * KDIM];
__device__ float g_sig[TSTEPS];
__device__ float g_WinT[FDIM * DIN];   // W_in transposed: [256][512]
__device__ float g_Wx[G4 * FDIM];      // W_ih[:, :256] repacked: [800][256]
__device__ float g_wy[G4];             // W_ih[:, 256]
__device__ float g_bsum[G4];           // b_ih + b_hh

// ---------------- small helpers ----------------
__device__ __forceinline__ float sigmoidf_(float x) { return 1.f / (1.f + __expf(-x)); }

__device__ __forceinline__ uint32_t smem_u32(const void* p) {
    return (uint32_t)__cvta_generic_to_shared(p);
}
__device__ __forceinline__ uint32_t my_cluster_rank() {
    uint32_t r; asm("mov.u32 %0, %%cluster_ctarank;" : "=r"(r)); return r;
}
__device__ __forceinline__ void dsmem_st_f32(uint32_t laddr, uint32_t peer, float v) {
    uint32_t ra;
    asm volatile("mapa.shared::cluster.u32 %0, %1, %2;" : "=r"(ra) : "r"(laddr), "r"(peer));
    asm volatile("st.shared::cluster.f32 [%0], %1;" :: "r"(ra), "f"(v) : "memory");
}
__device__ __forceinline__ void cluster_sync_() {
    asm volatile("barrier.cluster.arrive.aligned;" ::: "memory");
    asm volatile("barrier.cluster.wait.aligned;" ::: "memory");
}

// ---------------- prep: transpose W_in, repack W_ih, combine biases ----------------
__global__ void prep_kernel(const float* __restrict__ W_in, const float* __restrict__ W_ih,
                            const float* __restrict__ b_ih, const float* __restrict__ b_hh) {
    int idx = blockIdx.x * blockDim.x + threadIdx.x;
    if (idx < G4 * FDIM) {
        int n = idx / FDIM, k = idx % FDIM;
        g_Wx[idx] = W_ih[n * (FDIM + 1) + k];
    }
    if (idx < DIN * FDIM) {
        int k = idx / FDIM, n = idx % FDIM;
        g_WinT[n * DIN + k] = W_in[idx];
    }
    if (idx < G4) {
        g_wy[idx]   = W_ih[idx * (FDIM + 1) + FDIM];
        g_bsum[idx] = b_ih[idx] + b_hh[idx];
    }
}

// ---------------- generic C = A * B^T (+bias +y-term) ----------------
// A[M,K] row-major, B[N,K] row-major (16B-aligned rows), C[M,N] row-major
__device__ __forceinline__ void gemm_nt_body(
    const float* __restrict__ A, const float* __restrict__ B, float* __restrict__ C,
    int M, int N, int K,
    const float* __restrict__ bias, const float* __restrict__ yvec, const float* __restrict__ wy)
{
    __shared__ __align__(16) float As[16][64];
    __shared__ __align__(16) float Bs[16][64];
    const int m0 = blockIdx.y * 64, n0 = blockIdx.x * 64;
    const int tid = threadIdx.x;
    const int tx = tid % 16, ty = tid / 16;
    const int lr = tid / 4, lc4 = (tid % 4) * 4;

    float acc[4][4];
#pragma unroll
    for (int i = 0; i < 4; i++)
#pragma unroll
        for (int j = 0; j < 4; j++) acc[i][j] = 0.f;

    for (int k0 = 0; k0 < K; k0 += 16) {
        float4 av = *reinterpret_cast<const float4*>(A + (size_t)(m0 + lr) * K + k0 + lc4);
        As[lc4 + 0][lr] = av.x; As[lc4 + 1][lr] = av.y;
        As[lc4 + 2][lr] = av.z; As[lc4 + 3][lr] = av.w;
        float4 bv = make_float4(0.f, 0.f, 0.f, 0.f);
        if (n0 + lr < N) bv = *reinterpret_cast<const float4*>(B + (size_t)(n0 + lr) * K + k0 + lc4);
        Bs[lc4 + 0][lr] = bv.x; Bs[lc4 + 1][lr] = bv.y;
        Bs[lc4 + 2][lr] = bv.z; Bs[lc4 + 3][lr] = bv.w;
        __syncthreads();
#pragma unroll
        for (int kk = 0; kk < 16; kk++) {
            float4 a4 = *reinterpret_cast<const float4*>(&As[kk][ty * 4]);
            float4 b4 = *reinterpret_cast<const float4*>(&Bs[kk][tx * 4]);
            float aa[4] = {a4.x, a4.y, a4.z, a4.w};
            float bb[4] = {b4.x, b4.y, b4.z, b4.w};
#pragma unroll
            for (int i = 0; i < 4; i++)
#pragma unroll
                for (int j = 0; j < 4; j++) acc[i][j] = fmaf(aa[i], bb[j], acc[i][j]);
        }
        __syncthreads();
    }
#pragma unroll
    for (int i = 0; i < 4; i++) {
        int m = m0 + ty * 4 + i;
        float yv = 0.f;
        if (yvec) yv = (m == 0) ? 0.f : yvec[m - 1];
#pragma unroll
        for (int j = 0; j < 4; j++) {
            int n = n0 + tx * 4 + j;
            if (n < N) {
                float v = acc[i][j] + (bias ? bias[n] : 0.f);
                if (wy) v = fmaf(yv, wy[n], v);
                C[(size_t)m * N + n] = v;
            }
        }
    }
}

__global__ void __launch_bounds__(256) gemm1_kernel(const float* __restrict__ x,
                                                    const float* __restrict__ b_in) {
    gemm_nt_body(x, g_WinT, g_xs, TSTEPS, FDIM, DIN, b_in, nullptr, nullptr);
}
__global__ void __launch_bounds__(256) gemm2_kernel(const float* __restrict__ y) {
    gemm_nt_body(g_xs, g_Wx, g_gx, TSTEPS, G4, FDIM, g_bsum, y, g_wy);
}

// ---------------- LSTM: 8-CTA cluster, register-resident W_hh ----------------
__global__ void __cluster_dims__(CLSZ, 1, 1) __launch_bounds__(256, 1)
lstm_kernel(const float* __restrict__ W_hh)
{
    __shared__ __align__(8) float sh_h[2][HID];
    __shared__ float sh_part[RPC];
    __shared__ float sh_gate[RPC];

    const int tid = threadIdx.x;
    const uint32_t rank = my_cluster_rank();

    const bool act = tid < 2 * RPC;
    const int rl   = act ? (tid % RPC) : 0;   // local row 0..99
    const int cc   = act ? (tid / RPC) : 0;   // column chunk 0/1 (cols cc*100..cc*100+99)
    const int gate = rl / JPC;
    const int jj   = rl % JPC;
    const int grow = gate * HID + (int)rank * JPC + jj;  // global gate row

    float2 w2[50];
    if (act) {
        const float2* wp = reinterpret_cast<const float2*>(W_hh + (size_t)grow * HID + cc * 100);
#pragma unroll
        for (int q = 0; q < 50; q++) w2[q] = wp[q];
    }
    if (tid < HID) sh_h[0][tid] = 0.f;
    float cst = 0.f;
    __syncthreads();
    cluster_sync_();

    for (int t = 0; t < TSTEPS; t++) {
        const int buf = t & 1;
        float gxv = 0.f;
        if (act && cc == 0) gxv = g_gx[(size_t)t * G4 + grow];   // hidden under FMA

        if (act) {
            float a0 = 0.f, a1 = 0.f;
            const float2* h2 = reinterpret_cast<const float2*>(&sh_h[buf][cc * 100]);
#pragma unroll
            for (int q = 0; q < 50; q++) {
                float2 hv = h2[q];
                a0 = fmaf(w2[q].x, hv.x, a0);
                a1 = fmaf(w2[q].y, hv.y, a1);
            }
            if (cc == 1) sh_part[rl] = a0 + a1;
            else         sh_gate[rl] = a0 + a1 + gxv;
        }
        __syncthreads();

        if (tid < JPC) {
            float gi = sh_gate[tid]            + sh_part[tid];
            float gf = sh_gate[JPC + tid]      + sh_part[JPC + tid];
            float gg = sh_gate[2 * JPC + tid]  + sh_part[2 * JPC + tid];
            float go = sh_gate[3 * JPC + tid]  + sh_part[3 * JPC + tid];
            float si = sigmoidf_(gi), sf = sigmoidf_(gf), so = sigmoidf_(go);
            cst = sf * cst + si * tanhf(gg);
            float h = so * tanhf(cst);
            g_hid[(size_t)t * HID + (int)rank * JPC + tid] = h;
            uint32_t la = smem_u32(&sh_h[buf ^ 1][(int)rank * JPC + tid]);
#pragma unroll
            for (int p = 0; p < CLSZ; p++) dsmem_st_f32(la, (uint32_t)p, h);
        }
        cluster_sync_();
    }
}

// ---------------- keys / sigmas from hiddens ----------------
__global__ void __launch_bounds__(64) keys_kernel(const float* __restrict__ W_k,
                                                  const float* __restrict__ b_k,
                                                  const float* __restrict__ W_s,
                                                  const float* __restrict__ b_s) {
    const int t = blockIdx.x;
    const int k = threadIdx.x;
    __shared__ float hsh[HID];
    for (int i = k; i < HID; i += 64) hsh[i] = g_hid[(size_t)t * HID + i];
    __syncthreads();
    if (k < KDIM) {
        float s = b_k[k];
#pragma unroll 4
        for (int h = 0; h < HID; h++) s = fmaf(hsh[h], W_k[h * KDIM + k], s);
        float kk = tanhf(s);
        g_keys[t * KDIM + k] = kk;
        g_kn[t * KDIM + k]   = kk / fmaxf(fabsf(kk), EPSF);
    } else if (k == KDIM) {
        float s = b_s[0];
#pragma unroll 4
        for (int h = 0; h < HID; h++) s = fmaf(hsh[h], W_s[h], s);
        g_sig[t] = sigmoidf_(s);
    }
}

// ---------------- MANN scan (wlu == 1 identically; wu/gamma drop out) ----------------
__global__ void __launch_bounds__(NSLOT, 1) mann_kernel(float* __restrict__ out) {
    const int i = threadIdx.x;   // slot index
    __shared__ float sk[KDIM], skn[KDIM], swsum[4];
    __shared__ float ssig;

    float M[KDIM];
#pragma unroll
    for (int d = 0; d < KDIM; d++) M[d] = 1e-6f;
    float wr = (i == 0) ? 1.f : 0.f;

    for (int t = 0; t < TSTEPS; t++) {
        if (i < KDIM) {
            sk[i]  = g_keys[t * KDIM + i];
            skn[i] = g_kn[t * KDIM + i];
        }
        if (i == 0) ssig = g_sig[t];
        __syncthreads();

        const float sg = ssig;
        const float ww = fmaf(sg, wr, 1.f - sg);     // sigma*wr + (1-sigma)*1

        float n0 = 0.f, n1 = 0.f, n2 = 0.f, n3 = 0.f;
        float d0 = 0.f, d1 = 0.f, d2 = 0.f, d3 = 0.f;
#pragma unroll
        for (int d = 0; d < KDIM; d += 4) {
            M[d]     = fmaf(ww, sk[d],     M[d]);
            M[d + 1] = fmaf(ww, sk[d + 1], M[d + 1]);
            M[d + 2] = fmaf(ww, sk[d + 2], M[d + 2]);
            M[d + 3] = fmaf(ww, sk[d + 3], M[d + 3]);
            n0 = fmaf(M[d],     M[d],     n0);
            n1 = fmaf(M[d + 1], M[d + 1], n1);
            n2 = fmaf(M[d + 2], M[d + 2], n2);
            n3 = fmaf(M[d + 3], M[d + 3], n3);
            d0 = fmaf(M[d],     skn[d],     d0);
            d1 = fmaf(M[d + 1], skn[d + 1], d1);
            d2 = fmaf(M[d + 2], skn[d + 2], d2);
            d3 = fmaf(M[d + 3], skn[d + 3], d3);
        }
        float nrm = sqrtf((n0 + n1) + (n2 + n3));
        float dot = (d0 + d1) + (d2 + d3);
        float logit = dot / fmaxf(nrm, EPSF);
        // |logit| <= sqrt(40) ~ 6.33, so no max-subtraction needed
        float e = __expf(logit);

        float s = e;
#pragma unroll
        for (int off = 16; off > 0; off >>= 1) s += __shfl_xor_sync(0xffffffffu, s, off);
        if ((i & 31) == 0) swsum[i >> 5] = s;
        __syncthreads();
        float tot = (swsum[0] + swsum[1]) + (swsum[2] + swsum[3]);
        wr = e / tot;
    }

#pragma unroll
    for (int d = 0; d < KDIM; d++) out[i * KDIM + d] = M[d];
}

// ---------------- launch ----------------
extern "C" void kernel_launch(void* const* d_in, const int* in_sizes, int n_in,
                              void* d_out, int out_size) {
    const float* x    = (const float*)d_in[0];
    const float* y    = (const float*)d_in[1];
    const float* W_in = (const float*)d_in[2];
    const float* b_in = (const float*)d_in[3];
    const float* W_ih = (const float*)d_in[4];
    const float* W_hh = (const float*)d_in[5];
    const float* b_ih = (const float*)d_in[6];
    const float* b_hh = (const float*)d_in[7];
    const float* W_k  = (const float*)d_in[8];
    const float* b_k  = (const float*)d_in[9];
    const float* W_s  = (const float*)d_in[10];
    const float* b_s  = (const float*)d_in[11];
    // d_in[12] = gamma: provably unused (wlu mask is identically 1)

    prep_kernel<<<(G4 * FDIM + 255) / 256, 256>>>(W_in, W_ih, b_ih, b_hh);
    gemm1_kernel<<<dim3(FDIM / 64, TSTEPS / 64), 256>>>(x, b_in);
    gemm2_kernel<<<dim3((G4 + 63) / 64, TSTEPS / 64), 256>>>(y);
    lstm_kernel<<<CLSZ, 256>>>(W_hh);
    keys_kernel<<<TSTEPS, 64>>>(W_k, b_k, W_s, b_s);
    mann_kernel<<<1, NSLOT>>>((float*)d_out);
}